// round 1
// baseline (speedup 1.0000x reference)
#include <cuda_runtime.h>
#include <cuda_bf16.h>
#include <math.h>

// Equilibrium propagation: 256 serial iterations of two matvecs over W2[128,4096]
// plus Adam updates of h[128], o[4096].
//
// Strategy:
//  - Kernel A: xW1 = clip(x,0,1) @ W1 partials, 256 CTAs (HBM-bound, one time).
//  - Kernel B: persistent, 32 CTAs x 256 threads. Each CTA owns a 128-column
//    slice of W2 (fp32, smem, stride-129 column-major -> conflict-free in both
//    matvec directions). Per iteration:
//      threads 0..127 : y_j = r_h . W2[:,j], g_o, Adam update of o slice (regs)
//      threads 128..255: p_i = sum_j W2[i,j]*r_o[j]  -> global partial buffer
//    Cross-CTA exchange via per-CTA monotonic flags (no central barrier).
//    Every CTA redundantly sums the 32 partials in FIXED order and performs
//    the identical h Adam update (replicated deterministic state).

#define G      32      // persistent CTAs
#define T      256     // threads per CTA
#define HID    128
#define OUT    4096
#define COLS   128     // output columns per CTA (OUT/G)
#define IN     65536
#define XCTAS  256     // CTAs for the xW1 kernel
#define XROWS  (IN / XCTAS)   // 256 rows per CTA
#define STRIDE 129     // smem column stride (bank-conflict-free both ways)

__device__ float g_xpart[XCTAS * HID];
__device__ float g_hpart[2][G][HID];
__device__ int   g_flags[G];

// ---------------------------------------------------------------------------
// Kernel A: xW1 partials. Each CTA handles XROWS rows of W1 (row-major [IN,HID]).
// thread: col = t&127, rp = t>>7 (2 row-partitions). Also resets g_flags.
// ---------------------------------------------------------------------------
__global__ __launch_bounds__(256) void xw1_kernel(
    const float* __restrict__ x, const float* __restrict__ W1)
{
    __shared__ float tmp[HID];
    int t   = threadIdx.x;
    int col = t & (HID - 1);
    int rp  = t >> 7;
    int base = blockIdx.x * XROWS + rp * (XROWS / 2);

    float acc = 0.f;
#pragma unroll 4
    for (int k = 0; k < XROWS / 2; ++k) {
        int i = base + k;
        float xv = fminf(fmaxf(x[i], 0.f), 1.f);
        acc += xv * W1[(size_t)i * HID + col];
    }
    if (rp == 1) tmp[col] = acc;
    __syncthreads();
    if (rp == 0) g_xpart[blockIdx.x * HID + col] = acc + tmp[col];

    // reset exchange flags for the persistent kernel (stale from prior replay)
    if (blockIdx.x == 0 && t < G) g_flags[t] = 0;
}

// ---------------------------------------------------------------------------
// Kernel B: persistent iteration kernel.
// Dynamic smem: W2 slice, 128 cols x 128 rows, element (i,j_local) at
// W2s[j_local*STRIDE + i].
// ---------------------------------------------------------------------------
extern __shared__ float W2s[];

__global__ __launch_bounds__(T) void eqprop_kernel(
    const float* __restrict__ W2,
    const float* __restrict__ b_h,
    const float* __restrict__ b_out,
    const float* __restrict__ h0,
    const float* __restrict__ o0,
    const int*   __restrict__ n_it_p,
    const float* __restrict__ eps_p,
    float*       __restrict__ out)
{
    __shared__ float s_rh[HID];
    __shared__ float s_ro[COLS];

    const int t = threadIdx.x;
    const int c = blockIdx.x;

    // robust scalar reads
    int n_it = *n_it_p;
    if (!(n_it > 0 && n_it < (1 << 20))) {
        n_it = (int)__int_as_float(n_it);            // in case it arrived as f32
        if (!(n_it > 0 && n_it < (1 << 20))) n_it = 256;
    }
    const float eps = *eps_p;

    // --- load W2 slice into smem (transposed scatter, conflict-free stores) ---
    for (int idx = t; idx < HID * COLS; idx += T) {
        int i  = idx >> 7;        // row (hidden)
        int jl = idx & (COLS - 1);
        W2s[jl * STRIDE + i] = W2[(size_t)i * OUT + (size_t)c * COLS + jl];
    }

    // --- per-thread state init ---
    float hW = 0.f, hreg = 0.f, mh = 0.f, vh = 0.f, bh = 0.f;
    float oreg = 0.f, mo = 0.f, vo = 0.f, bo = 0.f;
    if (t < HID) {
        float s = 0.f;
#pragma unroll 8
        for (int k = 0; k < XCTAS; ++k) s += g_xpart[k * HID + t];
        hW   = s;
        hreg = h0[t];
        bh   = b_h[t];
        oreg = o0[c * COLS + t];
        bo   = b_out[c * COLS + t];
        s_rh[t] = fminf(fmaxf(hreg, 0.f), 1.f);
        s_ro[t] = fminf(fmaxf(oreg, 0.f), 1.f);
    }
    __syncthreads();

    volatile int* vflags = g_flags;
    float pw1 = 1.f, pw2 = 1.f;

    for (int it = 1; it <= n_it; ++it) {
        const int p = it & 1;
        pw1 *= 0.9f;
        pw2 *= 0.999f;

        float onew = 0.f, ronew = 0.f;

        if (t < HID) {
            // ---- pass 1: y_j = sum_i r_h[i] * W2[i, j],  j = t ----
            const float* wc = &W2s[t * STRIDE];
            float a0 = 0.f, a1 = 0.f, a2 = 0.f, a3 = 0.f;
#pragma unroll 8
            for (int i = 0; i < HID; i += 4) {
                a0 += wc[i]     * s_rh[i];
                a1 += wc[i + 1] * s_rh[i + 1];
                a2 += wc[i + 2] * s_rh[i + 2];
                a3 += wc[i + 3] * s_rh[i + 3];
            }
            float y  = (a0 + a1) + (a2 + a3);
            float ro = s_ro[t];
            float mask = (oreg >= 0.f && oreg <= 1.f) ? 1.f : 0.f;
            float g = mask * (ro - bo - y);
            mo = 0.9f * mo + 0.1f * g;
            vo = 0.999f * vo + 0.001f * g * g;
            float mhat = mo / (1.f - pw1);
            float vhat = vo / (1.f - pw2);
            onew  = oreg - eps * mhat / (sqrtf(vhat) + 1e-8f);
            ronew = fminf(fmaxf(onew, 0.f), 1.f);
        } else {
            // ---- pass 2: p_i = sum_j W2[i, j] * r_o[j],  i = t-128 ----
            const int i = t - HID;
            float a0 = 0.f, a1 = 0.f, a2 = 0.f, a3 = 0.f;
#pragma unroll 8
            for (int j = 0; j < COLS; j += 4) {
                a0 += W2s[j       * STRIDE + i] * s_ro[j];
                a1 += W2s[(j + 1) * STRIDE + i] * s_ro[j + 1];
                a2 += W2s[(j + 2) * STRIDE + i] * s_ro[j + 2];
                a3 += W2s[(j + 3) * STRIDE + i] * s_ro[j + 3];
            }
            g_hpart[p][c][i] = (a0 + a1) + (a2 + a3);
            __threadfence();   // publish partial at gpu scope
        }

        __syncthreads();       // pass2 done reading s_ro; partial STGs fenced

        if (t < HID) {         // now safe to advance o in smem
            oreg    = onew;
            s_ro[t] = ronew;
        }
        if (t == T - 1) vflags[c] = it;     // post our iteration flag

        // wait for all CTAs' partials of this iteration (flags are monotonic)
        if (t < G) {
            while (vflags[t] < it) { }
            __threadfence();   // acquire: order hpart loads after flag observe
        }
        __syncthreads();

        if (t < HID) {
            // fixed-order sum over 32 partials -> identical h in every CTA
            float s = 0.f;
#pragma unroll
            for (int k = 0; k < G; ++k) s += g_hpart[p][k][t];
            float rh   = fminf(fmaxf(hreg, 0.f), 1.f);
            float mask = (hreg >= 0.f && hreg <= 1.f) ? 1.f : 0.f;
            float g = mask * (rh - bh - hW - s);
            mh = 0.9f * mh + 0.1f * g;
            vh = 0.999f * vh + 0.001f * g * g;
            float mhat = mh / (1.f - pw1);
            float vhat = vh / (1.f - pw2);
            hreg = hreg - eps * mhat / (sqrtf(vhat) + 1e-8f);
            s_rh[t] = fminf(fmaxf(hreg, 0.f), 1.f);
        }
        __syncthreads();
    }

    if (t < HID) out[c * COLS + t] = oreg;
}

// ---------------------------------------------------------------------------
extern "C" void kernel_launch(void* const* d_in, const int* in_sizes, int n_in,
                              void* d_out, int out_size)
{
    const float* x    = (const float*)d_in[0];
    const float* W1   = (const float*)d_in[1];
    const float* W2   = (const float*)d_in[2];
    // d_in[3] = b_in (unused by the reference math)
    const float* b_h   = (const float*)d_in[4];
    const float* b_out = (const float*)d_in[5];
    const float* h0    = (const float*)d_in[6];
    const float* o0    = (const float*)d_in[7];
    const int*   n_it  = (const int*)d_in[8];
    const float* eps   = (const float*)d_in[9];
    float* out = (float*)d_out;

    static int configured = 0;
    const int smem_bytes = COLS * STRIDE * sizeof(float);   // 66,048 B
    if (!configured) {
        cudaFuncSetAttribute(eqprop_kernel,
                             cudaFuncAttributeMaxDynamicSharedMemorySize,
                             smem_bytes);
        configured = 1;
    }

    xw1_kernel<<<XCTAS, 256>>>(x, W1);
    eqprop_kernel<<<G, T, smem_bytes>>>(W2, b_h, b_out, h0, o0, n_it, eps, out);
}

// round 3
// speedup vs baseline: 1.9661x; 1.9661x over previous
#include <cuda_runtime.h>
#include <math.h>

// Equilibrium propagation, 256 serial iterations.
//   h[128] update needs full reduction of W2 @ r_o over all 4096 outputs.
//   o[4096] update needs W2^T @ r_h (local per column).
//
// Design (R2):
//  - 64 persistent CTAs, each owns 64 output columns. W2 slice kept in smem in
//    BOTH layouts (col-major pitch 132 for the o-matvec, row-major pitch 68
//    for the h-partial matvec) -> float4 LDS, 4-phase bank-optimal.
//  - Fence-free cross-CTA exchange: each h-partial is published as ONE 8-byte
//    word {tag=iteration, float value} via st.relaxed.gpu.b64 and polled with
//    ld.relaxed.gpu.b64 (single-copy atomic -> no membar / CCTL.IVALL).
//  - Role split: threads 0..127 own h (pass2 -> publish -> poll -> h Adam),
//    threads 128..191 own o (pass1 -> o Adam). Double-buffered s_rh / s_ro
//    => exactly one __syncthreads per iteration; the remote round trip
//    overlaps the o-side work.
//  - Every CTA redundantly reduces the 64 partials in a FIXED order, so the
//    replicated h state is bitwise identical in all CTAs (deterministic).

#define G      64
#define T      256
#define HID    128
#define OUT    4096
#define COLS   (OUT / G)      // 64
#define IN     65536
#define XCTAS  256
#define XROWS  (IN / XCTAS)   // 256

#define PITCH_C 132           // col-major column pitch (floats): 528B, 16B-mult
#define PITCH_R 68            // row-major row pitch (floats):    272B, 16B-mult

__device__ float g_xpart[XCTAS * HID];
__device__ unsigned long long g_part[2][G][HID];   // {tag, float} words

__device__ __forceinline__ unsigned long long ldx(const unsigned long long* p) {
    unsigned long long v;
    asm volatile("ld.relaxed.gpu.global.b64 %0, [%1];" : "=l"(v) : "l"(p) : "memory");
    return v;
}
__device__ __forceinline__ void stx(unsigned long long* p, unsigned long long v) {
    asm volatile("st.relaxed.gpu.global.b64 [%0], %1;" :: "l"(p), "l"(v) : "memory");
}
__device__ __forceinline__ float clampf(float v) {
    return fminf(fmaxf(v, 0.f), 1.f);
}

// ---------------------------------------------------------------------------
// Kernel A: xW1 partials (HBM-bound, one time). Also resets the tag words so
// graph replays can't observe stale {tag==it} matches.
// ---------------------------------------------------------------------------
__global__ __launch_bounds__(256) void xw1_kernel(
    const float* __restrict__ x, const float* __restrict__ W1)
{
    __shared__ float tmp[HID];
    int t   = threadIdx.x;
    int col = t & (HID - 1);
    int rp  = t >> 7;
    int base = blockIdx.x * XROWS + rp * (XROWS / 2);

    float acc = 0.f;
#pragma unroll 4
    for (int k = 0; k < XROWS / 2; ++k) {
        int i = base + k;
        float xv = clampf(x[i]);
        acc += xv * W1[(size_t)i * HID + col];
    }
    if (rp == 1) tmp[col] = acc;
    __syncthreads();
    if (rp == 0) g_xpart[blockIdx.x * HID + col] = acc + tmp[col];

    // reset partial tags (2 * G * HID = 16384 words; grid has 65536 threads)
    int gid = blockIdx.x * 256 + t;
    if (gid < 2 * G * HID)
        ((unsigned long long*)g_part)[gid] = 0ull;
}

// ---------------------------------------------------------------------------
// Kernel B: persistent iteration kernel. Dynamic smem: W2c then W2r.
// ---------------------------------------------------------------------------
extern __shared__ float smem_dyn[];

__global__ __launch_bounds__(T, 1) void eqprop_kernel(
    const float* __restrict__ W2,
    const float* __restrict__ b_h,
    const float* __restrict__ b_out,
    const float* __restrict__ h0,
    const float* __restrict__ o0,
    const int*   __restrict__ n_it_p,
    const float* __restrict__ eps_p,
    float*       __restrict__ out)
{
    float* W2c = smem_dyn;                         // [COLS][PITCH_C]
    float* W2r = smem_dyn + COLS * PITCH_C;        // [HID][PITCH_R]
    __shared__ __align__(16) float s_rh[2][HID];
    __shared__ __align__(16) float s_ro[2][COLS];

    const int t = threadIdx.x;
    const int c = blockIdx.x;

    int n_it = *n_it_p;
    if (!(n_it > 0 && n_it < (1 << 20))) {
        n_it = (int)__int_as_float(n_it);
        if (!(n_it > 0 && n_it < (1 << 20))) n_it = 256;
    }
    const float eps = *eps_p;

    // --- load W2 slice into both smem layouts (one-time, coalesced) ---
    for (int idx = t; idx < HID * COLS; idx += T) {
        int i = idx >> 6;            // hidden row
        int j = idx & (COLS - 1);    // local column
        float w = W2[(size_t)i * OUT + (size_t)c * COLS + j];
        W2c[j * PITCH_C + i] = w;
        W2r[i * PITCH_R + j] = w;
    }

    // --- per-thread state ---
    float hW = 0.f, hreg = 0.f, mh = 0.f, vh = 0.f, bh = 0.f;
    float oreg = 0.f, mo = 0.f, vo = 0.f, bo = 0.f;
    if (t < HID) {
        float s = 0.f;
#pragma unroll 16
        for (int k = 0; k < XCTAS; ++k) s += g_xpart[k * HID + t];
        hW   = s;
        hreg = h0[t];
        bh   = b_h[t];
        s_rh[1][t] = clampf(hreg);
    } else if (t < HID + COLS) {
        int j = t - HID;
        oreg = o0[c * COLS + j];
        bo   = b_out[c * COLS + j];
        s_ro[1][j] = clampf(oreg);
    }
    __syncthreads();

    float pw1 = 1.f, pw2 = 1.f;

    for (int it = 1; it <= n_it; ++it) {
        const int cur = it & 1;
        const int nxt = cur ^ 1;
        const int par = it & 1;
        pw1 *= 0.9f;
        pw2 *= 0.999f;
        const float ic1 = 1.f / (1.f - pw1);
        const float ic2 = 1.f / (1.f - pw2);

        if (t < HID) {
            // ---- pass 2: p_i = sum_j W2[i,j] * r_o[j] over this CTA's cols ----
            const float4* wr  = (const float4*)(W2r + t * PITCH_R);
            const float4* ro4 = (const float4*)(s_ro[cur]);
            float4 a = make_float4(0.f, 0.f, 0.f, 0.f);
#pragma unroll
            for (int q = 0; q < COLS / 4; ++q) {
                float4 w = wr[q], r = ro4[q];
                a.x += w.x * r.x; a.y += w.y * r.y;
                a.z += w.z * r.z; a.w += w.w * r.w;
            }
            float p = (a.x + a.y) + (a.z + a.w);
            unsigned long long mine =
                ((unsigned long long)(unsigned)it << 32) | (unsigned long long)__float_as_uint(p);
            stx(&g_part[par][c][t], mine);           // publish early

            // ---- poll all 64 partials (batched, fixed-order reduction) ----
            float acc0 = 0.f, acc1 = 0.f, acc2 = 0.f, acc3 = 0.f;
#pragma unroll
            for (int w2 = 0; w2 < G / 32; ++w2) {
                unsigned long long v[32];
#pragma unroll
                for (int k = 0; k < 32; ++k)
                    v[k] = ldx(&g_part[par][w2 * 32 + k][t]);
                if ((c >> 5) == w2) v[c & 31] = mine;   // own slot from reg
                bool redo = true;
                while (redo) {
                    redo = false;
#pragma unroll
                    for (int k = 0; k < 32; ++k) {
                        if ((int)(v[k] >> 32) != it) {
                            v[k] = ldx(&g_part[par][w2 * 32 + k][t]);
                            if ((int)(v[k] >> 32) != it) redo = true;
                        }
                    }
                }
#pragma unroll
                for (int k = 0; k < 32; ++k) {
                    float f = __uint_as_float((unsigned)v[k]);
                    switch (k & 3) {
                        case 0: acc0 += f; break;
                        case 1: acc1 += f; break;
                        case 2: acc2 += f; break;
                        default: acc3 += f; break;
                    }
                }
            }
            float S = (acc0 + acc1) + (acc2 + acc3);

            // ---- h Adam update (replicated, deterministic) ----
            float rh   = clampf(hreg);
            float mask = (hreg >= 0.f && hreg <= 1.f) ? 1.f : 0.f;
            float g    = mask * (rh - bh - hW - S);
            mh = 0.9f  * mh + 0.1f  * g;
            vh = 0.999f * vh + 0.001f * g * g;
            hreg -= eps * (mh * ic1) / (sqrtf(vh * ic2) + 1e-8f);
            s_rh[nxt][t] = clampf(hreg);
        } else if (t < HID + COLS) {
            // ---- pass 1: y_j = sum_i r_h[i] * W2[i,j]  (overlaps exchange) ----
            int j = t - HID;
            const float4* wc  = (const float4*)(W2c + j * PITCH_C);
            const float4* rh4 = (const float4*)(s_rh[cur]);
            float4 a = make_float4(0.f, 0.f, 0.f, 0.f);
#pragma unroll
            for (int q = 0; q < HID / 4; ++q) {
                float4 w = wc[q], r = rh4[q];
                a.x += w.x * r.x; a.y += w.y * r.y;
                a.z += w.z * r.z; a.w += w.w * r.w;
            }
            float y = (a.x + a.y) + (a.z + a.w);

            float ro   = clampf(oreg);
            float mask = (oreg >= 0.f && oreg <= 1.f) ? 1.f : 0.f;
            float g    = mask * (ro - bo - y);
            mo = 0.9f  * mo + 0.1f  * g;
            vo = 0.999f * vo + 0.001f * g * g;
            oreg -= eps * (mo * ic1) / (sqrtf(vo * ic2) + 1e-8f);
            s_ro[nxt][j] = clampf(oreg);
        }
        __syncthreads();
    }

    if (t >= HID && t < HID + COLS)
        out[c * COLS + (t - HID)] = oreg;
}

// ---------------------------------------------------------------------------
extern "C" void kernel_launch(void* const* d_in, const int* in_sizes, int n_in,
                              void* d_out, int out_size)
{
    const float* x     = (const float*)d_in[0];
    const float* W1    = (const float*)d_in[1];
    const float* W2    = (const float*)d_in[2];
    // d_in[3] = b_in (unused by the reference math)
    const float* b_h   = (const float*)d_in[4];
    const float* b_out = (const float*)d_in[5];
    const float* h0    = (const float*)d_in[6];
    const float* o0    = (const float*)d_in[7];
    const int*   n_it  = (const int*)d_in[8];
    const float* eps   = (const float*)d_in[9];
    float* out = (float*)d_out;

    static int configured = 0;
    const int smem_bytes = (COLS * PITCH_C + HID * PITCH_R) * sizeof(float); // 68,608
    if (!configured) {
        cudaFuncSetAttribute(eqprop_kernel,
                             cudaFuncAttributeMaxDynamicSharedMemorySize,
                             smem_bytes);
        configured = 1;
    }

    xw1_kernel<<<XCTAS, 256>>>(x, W1);
    eqprop_kernel<<<G, T, smem_bytes>>>(W2, b_h, b_out, h0, o0, n_it, eps, out);
}